// round 11
// baseline (speedup 1.0000x reference)
#include <cuda_runtime.h>
#include <cuda_fp16.h>
#include <cstdint>

// SharpenedCosineSimilarity forward via single-product fp16 mma.sync GEMM with
// implicit im2col. Warp tile 64x64, CTA tile 128x256, 1 CTA/SM.
// GEMM view: M=Cout=256, N=B*H*W=131072, K=Cin*9=1152 (k = tap*128 + cin).

#define CIN   128
#define COUT  256
#define HH    64
#define WW    64
#define BB    32
#define KTOT  1152
#define NTOT  (BB*HH*WW)
#define EPSF  1e-12f

#define MT    128
#define NT    256
#define KC    64
#define NKIT  (KTOT/KC)      // 18

#define ROWB  144            // bytes per smem row: 128 data + 16 pad (conflict-free ldmatrix)
#define TILEB_A (128*ROWB)   // 18432 B
#define TILEB_B (256*ROWB)   // 36864 B
#define STAGE_BYTES (TILEB_A + TILEB_B)   // 55296 B
#define SMEM_TOTAL  (2*STAGE_BYTES)       // 110592 B

// ---------------- device scratch (static; no allocations) ----------------
__device__ __half g_Ah[COUT * KTOT];           // weights fp16, k = tap*128+cin
__device__ __half g_xh[(size_t)NTOT * CIN];    // channel-last x fp16 (33.5MB, L2-resident)
__device__ float g_psqr[COUT];
__device__ float g_s[NTOT];
__device__ float g_invden[NTOT];

// ---------------- PTX helpers ----------------
static __device__ __forceinline__ uint32_t smem_u32(const void* p) {
    uint32_t a;
    asm("{ .reg .u64 t; cvta.to.shared.u64 t, %1; cvt.u32.u64 %0, t; }" : "=r"(a) : "l"(p));
    return a;
}
#define CP_ASYNC16(s, g) \
    asm volatile("cp.async.cg.shared.global [%0], [%1], 16;" :: "r"(s), "l"(g) : "memory")
#define CP_ASYNC16_Z(s, g, sz) \
    asm volatile("cp.async.cg.shared.global [%0], [%1], 16, %2;" :: "r"(s), "l"(g), "r"(sz) : "memory")
#define CP_COMMIT()  asm volatile("cp.async.commit_group;" ::: "memory")
#define CP_WAIT(n)   asm volatile("cp.async.wait_group %0;" :: "n"(n) : "memory")

#define LDSM4(r0, r1, r2, r3, a) \
    asm volatile("ldmatrix.sync.aligned.m8n8.x4.shared.b16 {%0,%1,%2,%3}, [%4];" \
        : "=r"(r0), "=r"(r1), "=r"(r2), "=r"(r3) : "r"(a))

static __device__ __forceinline__ void mma_f16(float* d, const uint32_t* a,
                                               uint32_t b0, uint32_t b1) {
    asm volatile(
        "mma.sync.aligned.m16n8k16.row.col.f32.f16.f16.f32 "
        "{%0,%1,%2,%3}, {%4,%5,%6,%7}, {%8,%9}, {%0,%1,%2,%3};"
        : "+f"(d[0]), "+f"(d[1]), "+f"(d[2]), "+f"(d[3])
        : "r"(a[0]), "r"(a[1]), "r"(a[2]), "r"(a[3]), "r"(b0), "r"(b1));
}

// ---------------- prep kernels ----------------
__global__ void prep_w(const float* __restrict__ w,
                       const float* __restrict__ p,
                       const float* __restrict__ q) {
    __shared__ float red[4];
    const int co = blockIdx.x;
    const int tid = threadIdx.x;  // 128
    const float* wr = w + co * KTOT;  // layout [Cin][3][3] per cout
    float ssum = 0.f;
    for (int i = tid; i < KTOT; i += 128) { const float v = wr[i]; ssum += v * v; }
    #pragma unroll
    for (int o = 16; o; o >>= 1) ssum += __shfl_xor_sync(0xffffffff, ssum, o);
    if ((tid & 31) == 0) red[tid >> 5] = ssum;
    __syncthreads();
    const float tot = red[0] + red[1] + red[2] + red[3];
    const float qv = q[0] * 0.01f;
    const float qs = qv * qv;
    const float scale = 1.f / (sqrtf(tot) + EPSF + qs);
    for (int i = tid; i < KTOT; i += 128) {
        const int cin = i / 9;
        const int t = i - cin * 9;
        const int k = t * 128 + cin;     // reordered K axis
        g_Ah[co * KTOT + k] = __float2half(wr[i] * scale);
    }
    if (tid == 0) { const float pv = p[co] * 0.1f; g_psqr[co] = pv * pv; }
}

// x[b][cin][h][w] -> xT[b][h][w][cin] fp16. 32x32 tiled transpose.
__global__ void __launch_bounds__(256)
prep_split(const float* __restrict__ x) {
    __shared__ float xs[32][33];
    const int b  = blockIdx.z;
    const int c0 = blockIdx.y * 32;
    const int p0 = blockIdx.x * 32;   // hw tile base
    const int tx = threadIdx.x & 31, ty = threadIdx.x >> 5;  // 32 x 8

    #pragma unroll
    for (int i = 0; i < 4; ++i) {
        const int c = ty + i * 8;
        xs[c][tx] = x[((size_t)b * CIN + c0 + c) * 4096 + p0 + tx];
    }
    __syncthreads();

    const int p  = threadIdx.x >> 3;       // pixel within tile
    const int g4 = (threadIdx.x & 7) * 4;  // cin group of 4
    uint2 hv;
    __half* ph = (__half*)&hv;
    #pragma unroll
    for (int j = 0; j < 4; ++j) ph[j] = __float2half(xs[g4 + j][p]);
    const size_t o = ((size_t)b * 4096 + p0 + p) * CIN + c0 + g4;
    *(uint2*)((char*)g_xh + o * 2) = hv;
}

__global__ void prep_s(const float* __restrict__ x) {
    const int i = blockIdx.x * 256 + threadIdx.x;
    const int b = i >> 12;
    const int hw = i & 4095;
    const float* xp = x + (size_t)b * CIN * 4096 + hw;
    float ssum = 0.f;
    #pragma unroll 8
    for (int c = 0; c < CIN; ++c) { const float v = xp[c * 4096]; ssum += v * v; }
    g_s[i] = ssum;
}

__global__ void prep_invden(const float* __restrict__ q) {
    const int i = blockIdx.x * 256 + threadIdx.x;
    const int b = i >> 12;
    const int hw = i & 4095;
    const int h = hw >> 6, w = hw & 63;
    const float* sp = g_s + b * 4096;
    float acc = 0.f;
    #pragma unroll
    for (int dh = -1; dh <= 1; ++dh) {
        const int hh = h + dh;
        if ((unsigned)hh >= (unsigned)HH) continue;
        #pragma unroll
        for (int dw = -1; dw <= 1; ++dw) {
            const int w2 = w + dw;
            if ((unsigned)w2 >= (unsigned)WW) continue;
            acc += sp[hh * 64 + w2];
        }
    }
    const float qv = q[0] * 0.01f;
    const float qs = qv * qv;
    g_invden[i] = 1.f / (sqrtf(acc + EPSF) + qs);
}

// ---------------- GEMM + fused epilogue ----------------
static __device__ __forceinline__ float scs_act(float y, float psqr) {
    const float sg = __fdividef(1.f, 1.f + __expf(-y));
    const float mag = exp2f(psqr * __log2f(fabsf(y) + EPSF));
    return sg * mag;
}

// Stage one KC=64 chunk: A from reordered weights, B implicitly from xT
// (tap-shifted window, zero-filled halo via cp.async src-size).
static __device__ __forceinline__ void stage_load(uint32_t sb, int m0, int n0,
                                                  int kit, int tid) {
    const int k0 = kit * KC;
    // ---- A: 128 rows x 8 x 16B ----
    #pragma unroll
    for (int rep = 0; rep < 4; ++rep) {
        const int idx = rep * 256 + tid;
        const int c   = idx & 7;
        const int row = idx >> 3;
        const uint32_t sa = sb + row * ROWB + c * 16;
        const char* g = (const char*)g_Ah
                      + ((size_t)(m0 + row) * KTOT + k0) * 2 + c * 16;
        CP_ASYNC16(sa, g);
    }
    // ---- B: implicit im2col from xT, 256 rows x 8 x 16B ----
    const int t    = kit >> 1;          // tap 0..8
    const int cinb = (kit & 1) * 64;    // cin block
    const int dh = t / 3 - 1;
    const int dw = t - (t / 3) * 3 - 1;
    const int b  = n0 >> 12;
    const int h0 = (n0 & 4095) >> 6;    // first of 4 output rows
    #pragma unroll
    for (int rep = 0; rep < 8; ++rep) {
        const int idx = rep * 256 + tid;
        const int c   = idx & 7;
        const int row = idx >> 3;          // pixel within tile (0..255)
        const uint32_t sa = sb + TILEB_A + row * ROWB + c * 16;
        const int h = h0 + (row >> 6) + dh;
        const int w = (row & 63) + dw;
        const bool ok = ((unsigned)h < (unsigned)HH) && ((unsigned)w < (unsigned)WW);
        const int hc = ok ? h : 0;
        const int wc = ok ? w : 0;
        const size_t off =
            (((size_t)b * 4096 + hc * 64 + wc) * CIN + cinb + c * 8) * 2;
        const char* g = (const char*)g_xh + off;
        const int sz = ok ? 16 : 0;
        CP_ASYNC16_Z(sa, g, sz);
    }
    CP_COMMIT();
}

__global__ void __launch_bounds__(256, 1)
conv_mma(float* __restrict__ out) {
    extern __shared__ char smem[];
    const uint32_t sbase = smem_u32(smem);
    const int tid = threadIdx.x;
    const int lane = tid & 31;
    const int wid = tid >> 5;
    const int warp_m = wid >> 2;    // 0..1 -> m offset 64
    const int warp_n = wid & 3;     // 0..3 -> n offset 64
    const int m0 = blockIdx.x * MT;
    const int n0 = blockIdx.y * NT;

    float acc[4][8][4];
    #pragma unroll
    for (int i = 0; i < 4; ++i)
        #pragma unroll
        for (int j = 0; j < 8; ++j)
            #pragma unroll
            for (int k = 0; k < 4; ++k) acc[i][j][k] = 0.f;

    stage_load(sbase, m0, n0, 0, tid);
    stage_load(sbase + STAGE_BYTES, m0, n0, 1, tid);

    const int lrow = lane & 15;
    const int lkg  = lane >> 4;

    #pragma unroll 1
    for (int kit = 0; kit < NKIT; ++kit) {
        if (kit < NKIT - 2) CP_WAIT(1); else CP_WAIT(0);
        __syncthreads();
        const uint32_t sb = sbase + (kit & 1) * STAGE_BYTES;
        const uint32_t sB = sb + TILEB_A;

        #pragma unroll
        for (int ks = 0; ks < 4; ++ks) {
            const uint32_t kb = ks * 32 + lkg * 16;
            uint32_t bh[4][4];
            #pragma unroll
            for (int np = 0; np < 4; ++np) {
                const uint32_t boff = (warp_n * 64 + np * 16 + lrow) * ROWB + kb;
                LDSM4(bh[np][0], bh[np][1], bh[np][2], bh[np][3], sB + boff);
            }
            #pragma unroll
            for (int ma = 0; ma < 4; ++ma) {
                const uint32_t aoff = (warp_m * 64 + ma * 16 + lrow) * ROWB + kb;
                uint32_t ah[4];
                LDSM4(ah[0], ah[1], ah[2], ah[3], sb + aoff);
                #pragma unroll
                for (int na = 0; na < 8; ++na) {
                    const int np = na >> 1;
                    const int hi = na & 1;  // 0: {r0,r2}, 1: {r1,r3}
                    mma_f16(acc[ma][na], ah, bh[np][hi], bh[np][hi + 2]);
                }
            }
        }
        __syncthreads();
        if (kit + 2 < NKIT)
            stage_load(sbase + (kit & 1) * STAGE_BYTES, m0, n0, kit + 2, tid);
    }

    // ---- epilogue ----
    const int b = n0 >> 12;
    const int hwbase = n0 & 4095;
    #pragma unroll
    for (int ma = 0; ma < 4; ++ma) {
        const int mrow = warp_m * 64 + ma * 16 + (lane >> 2);
        #pragma unroll
        for (int na = 0; na < 8; ++na) {
            const int nloc = warp_n * 64 + na * 8 + 2 * (lane & 3);
            const float2 inv = *(const float2*)&g_invden[n0 + nloc];
            #pragma unroll
            for (int h = 0; h < 2; ++h) {
                const int co = m0 + mrow + h * 8;
                const float psqr = g_psqr[co];
                float2 o2;
                o2.x = scs_act(acc[ma][na][h * 2 + 0] * inv.x, psqr);
                o2.y = scs_act(acc[ma][na][h * 2 + 1] * inv.y, psqr);
                *(float2*)&out[(((size_t)b * COUT + co) << 12) + hwbase + nloc] = o2;
            }
        }
    }
}

// ---------------- launch ----------------
extern "C" void kernel_launch(void* const* d_in, const int* in_sizes, int n_in,
                              void* d_out, int out_size) {
    const float *x = nullptr, *w = nullptr, *p = nullptr, *q = nullptr;
    for (int i = 0; i < n_in; ++i) {
        const int sz = in_sizes[i];
        if (sz == BB * CIN * HH * WW)      x = (const float*)d_in[i];
        else if (sz == COUT * CIN * 9)     w = (const float*)d_in[i];
        else if (sz == COUT)               p = (const float*)d_in[i];
        else if (sz == 1)                  q = (const float*)d_in[i];
    }
    float* out = (float*)d_out;

    cudaFuncSetAttribute(conv_mma, cudaFuncAttributeMaxDynamicSharedMemorySize,
                         SMEM_TOTAL);

    prep_w<<<COUT, 128>>>(w, p, q);
    prep_split<<<dim3(128, 4, 32), 256>>>(x);
    prep_s<<<NTOT / 256, 256>>>(x);
    prep_invden<<<NTOT / 256, 256>>>(q);

    dim3 grid(2, NTOT / NT);  // M fastest: both M-tiles of an N-tile adjacent (L2 reuse of B)
    conv_mma<<<grid, 256, SMEM_TOTAL>>>(out);
}

// round 13
// speedup vs baseline: 1.2239x; 1.2239x over previous
#include <cuda_runtime.h>
#include <cuda_fp16.h>
#include <cstdint>

// SharpenedCosineSimilarity forward via single-product fp16 mma.sync GEMM with
// implicit im2col. Warp tile 64x32 (R9 shape), 3-stage cp.async pipeline with
// one barrier per K-iteration. prep_s fused into prep_split.
// GEMM view: M=Cout=256, N=B*H*W=131072, K=Cin*9=1152 (k = tap*128 + cin).

#define CIN   128
#define COUT  256
#define HH    64
#define WW    64
#define BB    32
#define KTOT  1152
#define NTOT  (BB*HH*WW)
#define EPSF  1e-12f

#define MT    128
#define NT    128
#define KC    64
#define NKIT  (KTOT/KC)      // 18

#define ROWB  144            // bytes per smem row: 128 data + 16 pad (conflict-free ldmatrix)
#define TILEB (128*ROWB)     // one 128-row tile = 18432 B
#define STAGE_BYTES (2*TILEB) // A|B = 36864 B
#define SMEM_TOTAL  (3*STAGE_BYTES)   // 110592 B (3 stages)

// ---------------- device scratch (static; no allocations) ----------------
__device__ __half g_Ah[COUT * KTOT];           // weights fp16, k = tap*128+cin
__device__ __half g_xh[(size_t)NTOT * CIN];    // channel-last x fp16 (33.5MB, L2-resident)
__device__ float g_psqr[COUT];
__device__ float g_s4[4][NTOT];                // partial sum_c x^2 (32 cins each)
__device__ float g_invden[NTOT];

// ---------------- PTX helpers ----------------
static __device__ __forceinline__ uint32_t smem_u32(const void* p) {
    uint32_t a;
    asm("{ .reg .u64 t; cvta.to.shared.u64 t, %1; cvt.u32.u64 %0, t; }" : "=r"(a) : "l"(p));
    return a;
}
#define CP_ASYNC16(s, g) \
    asm volatile("cp.async.cg.shared.global [%0], [%1], 16;" :: "r"(s), "l"(g) : "memory")
#define CP_ASYNC16_Z(s, g, sz) \
    asm volatile("cp.async.cg.shared.global [%0], [%1], 16, %2;" :: "r"(s), "l"(g), "r"(sz) : "memory")
#define CP_COMMIT()  asm volatile("cp.async.commit_group;" ::: "memory")
#define CP_WAIT(n)   asm volatile("cp.async.wait_group %0;" :: "n"(n) : "memory")

#define LDSM4(r0, r1, r2, r3, a) \
    asm volatile("ldmatrix.sync.aligned.m8n8.x4.shared.b16 {%0,%1,%2,%3}, [%4];" \
        : "=r"(r0), "=r"(r1), "=r"(r2), "=r"(r3) : "r"(a))

static __device__ __forceinline__ void mma_f16(float* d, const uint32_t* a,
                                               uint32_t b0, uint32_t b1) {
    asm volatile(
        "mma.sync.aligned.m16n8k16.row.col.f32.f16.f16.f32 "
        "{%0,%1,%2,%3}, {%4,%5,%6,%7}, {%8,%9}, {%0,%1,%2,%3};"
        : "+f"(d[0]), "+f"(d[1]), "+f"(d[2]), "+f"(d[3])
        : "r"(a[0]), "r"(a[1]), "r"(a[2]), "r"(a[3]), "r"(b0), "r"(b1));
}

// ---------------- prep kernels ----------------
__global__ void prep_w(const float* __restrict__ w,
                       const float* __restrict__ p,
                       const float* __restrict__ q) {
    __shared__ float red[4];
    const int co = blockIdx.x;
    const int tid = threadIdx.x;  // 128
    const float* wr = w + co * KTOT;  // layout [Cin][3][3] per cout
    float ssum = 0.f;
    for (int i = tid; i < KTOT; i += 128) { const float v = wr[i]; ssum += v * v; }
    #pragma unroll
    for (int o = 16; o; o >>= 1) ssum += __shfl_xor_sync(0xffffffff, ssum, o);
    if ((tid & 31) == 0) red[tid >> 5] = ssum;
    __syncthreads();
    const float tot = red[0] + red[1] + red[2] + red[3];
    const float qv = q[0] * 0.01f;
    const float qs = qv * qv;
    const float scale = 1.f / (sqrtf(tot) + EPSF + qs);
    for (int i = tid; i < KTOT; i += 128) {
        const int cin = i / 9;
        const int t = i - cin * 9;
        const int k = t * 128 + cin;     // reordered K axis
        g_Ah[co * KTOT + k] = __float2half(wr[i] * scale);
    }
    if (tid == 0) { const float pv = p[co] * 0.1f; g_psqr[co] = pv * pv; }
}

// x[b][cin][h][w] -> xT[b][h][w][cin] fp16, plus partial x^2 sums over the
// 32-cin chunk into g_s4[chunk]. 32x32 tiled transpose.
__global__ void __launch_bounds__(256)
prep_split(const float* __restrict__ x) {
    __shared__ float xs[32][33];
    const int b  = blockIdx.z;
    const int yc = blockIdx.y;        // cin chunk 0..3
    const int c0 = yc * 32;
    const int p0 = blockIdx.x * 32;   // hw tile base
    const int tx = threadIdx.x & 31, ty = threadIdx.x >> 5;  // 32 x 8

    #pragma unroll
    for (int i = 0; i < 4; ++i) {
        const int c = ty + i * 8;
        xs[c][tx] = x[((size_t)b * CIN + c0 + c) * 4096 + p0 + tx];
    }
    __syncthreads();

    const int p  = threadIdx.x >> 3;       // pixel within tile
    const int g4 = (threadIdx.x & 7) * 4;  // cin group of 4
    uint2 hv;
    __half* ph = (__half*)&hv;
    float part = 0.f;
    #pragma unroll
    for (int j = 0; j < 4; ++j) {
        const float v = xs[g4 + j][p];
        ph[j] = __float2half(v);
        part += v * v;
    }
    const size_t o = ((size_t)b * 4096 + p0 + p) * CIN + c0 + g4;
    *(uint2*)((char*)g_xh + o * 2) = hv;

    // reduce 8 lanes (same pixel) -> partial sum of this 32-cin chunk
    part += __shfl_xor_sync(0xffffffff, part, 1);
    part += __shfl_xor_sync(0xffffffff, part, 2);
    part += __shfl_xor_sync(0xffffffff, part, 4);
    if ((threadIdx.x & 7) == 0)
        g_s4[yc][(size_t)b * 4096 + p0 + p] = part;
}

__global__ void prep_invden(const float* __restrict__ q) {
    const int i = blockIdx.x * 256 + threadIdx.x;
    const int b = i >> 12;
    const int hw = i & 4095;
    const int h = hw >> 6, w = hw & 63;
    float acc = 0.f;
    #pragma unroll
    for (int dh = -1; dh <= 1; ++dh) {
        const int hh = h + dh;
        if ((unsigned)hh >= (unsigned)HH) continue;
        #pragma unroll
        for (int dw = -1; dw <= 1; ++dw) {
            const int w2 = w + dw;
            if ((unsigned)w2 >= (unsigned)WW) continue;
            const int idx = b * 4096 + hh * 64 + w2;
            acc += g_s4[0][idx] + g_s4[1][idx] + g_s4[2][idx] + g_s4[3][idx];
        }
    }
    const float qv = q[0] * 0.01f;
    const float qs = qv * qv;
    g_invden[i] = 1.f / (sqrtf(acc + EPSF) + qs);
}

// ---------------- GEMM + fused epilogue ----------------
static __device__ __forceinline__ float scs_act(float y, float psqr) {
    const float sg = __fdividef(1.f, 1.f + __expf(-y));
    const float mag = exp2f(psqr * __log2f(fabsf(y) + EPSF));
    return sg * mag;
}

// Stage one KC=64 chunk: A from reordered weights, B implicitly from xT
// (tap-shifted window, zero-filled halo via cp.async src-size).
static __device__ __forceinline__ void stage_load(uint32_t sb, int m0, int n0,
                                                  int kit, int tid) {
    const int k0 = kit * KC;
    // ---- A: 128 rows x 8 x 16B ----
    #pragma unroll
    for (int rep = 0; rep < 4; ++rep) {
        const int idx = rep * 256 + tid;
        const int c   = idx & 7;
        const int row = idx >> 3;
        const uint32_t sa = sb + row * ROWB + c * 16;
        const char* g = (const char*)g_Ah
                      + ((size_t)(m0 + row) * KTOT + k0) * 2 + c * 16;
        CP_ASYNC16(sa, g);
    }
    // ---- B: implicit im2col from xT, 128 rows x 8 x 16B ----
    const int t    = kit >> 1;          // tap 0..8
    const int cinb = (kit & 1) * 64;    // cin block
    const int dh = t / 3 - 1;
    const int dw = t - (t / 3) * 3 - 1;
    const int b  = n0 >> 12;
    const int h0 = (n0 & 4095) >> 6;    // first of 2 output rows
    #pragma unroll
    for (int rep = 0; rep < 4; ++rep) {
        const int idx = rep * 256 + tid;
        const int c   = idx & 7;
        const int row = idx >> 3;          // pixel within tile
        const uint32_t sa = sb + TILEB + row * ROWB + c * 16;
        const int h = h0 + (row >> 6) + dh;
        const int w = (row & 63) + dw;
        const bool ok = ((unsigned)h < (unsigned)HH) && ((unsigned)w < (unsigned)WW);
        const int hc = ok ? h : 0;
        const int wc = ok ? w : 0;
        const size_t off =
            (((size_t)b * 4096 + hc * 64 + wc) * CIN + cinb + c * 8) * 2;
        const char* g = (const char*)g_xh + off;
        const int sz = ok ? 16 : 0;
        CP_ASYNC16_Z(sa, g, sz);
    }
    CP_COMMIT();
}

__global__ void __launch_bounds__(256, 2)
conv_mma(float* __restrict__ out) {
    extern __shared__ char smem[];
    const uint32_t sbase = smem_u32(smem);
    const int tid = threadIdx.x;
    const int lane = tid & 31;
    const int wid = tid >> 5;
    const int warp_m = wid >> 2;    // 0..1
    const int warp_n = wid & 3;     // 0..3
    const int m0 = blockIdx.x * MT;
    const int n0 = blockIdx.y * NT;

    float acc[4][4][4];
    #pragma unroll
    for (int i = 0; i < 4; ++i)
        #pragma unroll
        for (int j = 0; j < 4; ++j)
            #pragma unroll
            for (int k = 0; k < 4; ++k) acc[i][j][k] = 0.f;

    stage_load(sbase, m0, n0, 0, tid);
    stage_load(sbase + STAGE_BYTES, m0, n0, 1, tid);

    const int lrow = lane & 15;
    const int lkg  = lane >> 4;

    int s_cur = 0;   // buffer holding stage kit
    int s_pf  = 2;   // buffer to prefetch kit+2 into

    #pragma unroll 1
    for (int kit = 0; kit < NKIT; ++kit) {
        if (kit < NKIT - 1) CP_WAIT(1); else CP_WAIT(0);
        __syncthreads();   // stage kit visible; readers of buffer s_pf (kit-1) done

        if (kit + 2 < NKIT)
            stage_load(sbase + s_pf * STAGE_BYTES, m0, n0, kit + 2, tid);

        const uint32_t sb = sbase + s_cur * STAGE_BYTES;
        const uint32_t sB = sb + TILEB;

        #pragma unroll
        for (int ks = 0; ks < 4; ++ks) {
            const uint32_t kb = ks * 32 + lkg * 16;
            uint32_t bh[2][4];
            #pragma unroll
            for (int np = 0; np < 2; ++np) {
                const uint32_t boff = (warp_n * 32 + np * 16 + lrow) * ROWB + kb;
                LDSM4(bh[np][0], bh[np][1], bh[np][2], bh[np][3], sB + boff);
            }
            #pragma unroll
            for (int ma = 0; ma < 4; ++ma) {
                const uint32_t aoff = (warp_m * 64 + ma * 16 + lrow) * ROWB + kb;
                uint32_t ah[4];
                LDSM4(ah[0], ah[1], ah[2], ah[3], sb + aoff);
                #pragma unroll
                for (int na = 0; na < 4; ++na) {
                    const int np = na >> 1;
                    const int hi = na & 1;  // 0: {r0,r2}, 1: {r1,r3}
                    mma_f16(acc[ma][na], ah, bh[np][hi], bh[np][hi + 2]);
                }
            }
        }
        s_cur = (s_cur == 2) ? 0 : s_cur + 1;
        s_pf  = (s_pf == 2) ? 0 : s_pf + 1;
    }

    // ---- epilogue ----
    const int b = n0 >> 12;
    const int hwbase = n0 & 4095;
    #pragma unroll
    for (int ma = 0; ma < 4; ++ma) {
        const int mrow = warp_m * 64 + ma * 16 + (lane >> 2);
        #pragma unroll
        for (int na = 0; na < 4; ++na) {
            const int nloc = warp_n * 32 + na * 8 + 2 * (lane & 3);
            const float2 inv = *(const float2*)&g_invden[n0 + nloc];
            #pragma unroll
            for (int h = 0; h < 2; ++h) {
                const int co = m0 + mrow + h * 8;
                const float psqr = g_psqr[co];
                float2 o2;
                o2.x = scs_act(acc[ma][na][h * 2 + 0] * inv.x, psqr);
                o2.y = scs_act(acc[ma][na][h * 2 + 1] * inv.y, psqr);
                *(float2*)&out[(((size_t)b * COUT + co) << 12) + hwbase + nloc] = o2;
            }
        }
    }
}

// ---------------- launch ----------------
extern "C" void kernel_launch(void* const* d_in, const int* in_sizes, int n_in,
                              void* d_out, int out_size) {
    const float *x = nullptr, *w = nullptr, *p = nullptr, *q = nullptr;
    for (int i = 0; i < n_in; ++i) {
        const int sz = in_sizes[i];
        if (sz == BB * CIN * HH * WW)      x = (const float*)d_in[i];
        else if (sz == COUT * CIN * 9)     w = (const float*)d_in[i];
        else if (sz == COUT)               p = (const float*)d_in[i];
        else if (sz == 1)                  q = (const float*)d_in[i];
    }
    float* out = (float*)d_out;

    cudaFuncSetAttribute(conv_mma, cudaFuncAttributeMaxDynamicSharedMemorySize,
                         SMEM_TOTAL);

    prep_w<<<COUT, 128>>>(w, p, q);
    prep_split<<<dim3(128, 4, 32), 256>>>(x);
    prep_invden<<<NTOT / 256, 256>>>(q);

    dim3 grid(2, NTOT / NT);  // M fastest: both M-tiles of an N-tile adjacent (L2 reuse of B)
    conv_mma<<<grid, 256, SMEM_TOTAL>>>(out);
}

// round 16
// speedup vs baseline: 1.2596x; 1.0292x over previous
#include <cuda_runtime.h>
#include <cuda_fp16.h>
#include <cstdint>

// SharpenedCosineSimilarity forward via single-product fp16 mma.sync GEMM with
// implicit im2col. Warp tile 64x32, 3-stage cp.async pipeline, one barrier per
// K-iteration, hoisted/incremental staging address math (ALU-pipe relief).
// GEMM view: M=Cout=256, N=B*H*W=131072, K=Cin*9=1152 (k = tap*128 + cin).

#define CIN   128
#define COUT  256
#define HH    64
#define WW    64
#define BB    32
#define KTOT  1152
#define NTOT  (BB*HH*WW)
#define EPSF  1e-12f

#define MT    128
#define NT    128
#define KC    64
#define NKIT  (KTOT/KC)      // 18

#define ROWB  144            // bytes per smem row: 128 data + 16 pad (conflict-free ldmatrix)
#define TILEB (128*ROWB)     // one 128-row tile = 18432 B
#define STAGE_BYTES (2*TILEB) // A|B = 36864 B
#define SMEM_TOTAL  (3*STAGE_BYTES)   // 110592 B (3 stages)

// ---------------- device scratch (static; no allocations) ----------------
__device__ __half g_Ah[COUT * KTOT];           // weights fp16, k = tap*128+cin
__device__ __half g_xh[(size_t)NTOT * CIN];    // channel-last x fp16 (33.5MB, L2-resident)
__device__ float g_psqr[COUT];
__device__ float g_s4[4][NTOT];                // partial sum_c x^2 (32 cins each)
__device__ float g_invden[NTOT];

// ---------------- PTX helpers ----------------
static __device__ __forceinline__ uint32_t smem_u32(const void* p) {
    uint32_t a;
    asm("{ .reg .u64 t; cvta.to.shared.u64 t, %1; cvt.u32.u64 %0, t; }" : "=r"(a) : "l"(p));
    return a;
}
#define CP_ASYNC16(s, g) \
    asm volatile("cp.async.cg.shared.global [%0], [%1], 16;" :: "r"(s), "l"(g) : "memory")
#define CP_ASYNC16_Z(s, g, sz) \
    asm volatile("cp.async.cg.shared.global [%0], [%1], 16, %2;" :: "r"(s), "l"(g), "r"(sz) : "memory")
#define CP_COMMIT()  asm volatile("cp.async.commit_group;" ::: "memory")
#define CP_WAIT(n)   asm volatile("cp.async.wait_group %0;" :: "n"(n) : "memory")

#define LDSM4(r0, r1, r2, r3, a) \
    asm volatile("ldmatrix.sync.aligned.m8n8.x4.shared.b16 {%0,%1,%2,%3}, [%4];" \
        : "=r"(r0), "=r"(r1), "=r"(r2), "=r"(r3) : "r"(a))

static __device__ __forceinline__ void mma_f16(float* d, const uint32_t* a,
                                               uint32_t b0, uint32_t b1) {
    asm volatile(
        "mma.sync.aligned.m16n8k16.row.col.f32.f16.f16.f32 "
        "{%0,%1,%2,%3}, {%4,%5,%6,%7}, {%8,%9}, {%0,%1,%2,%3};"
        : "+f"(d[0]), "+f"(d[1]), "+f"(d[2]), "+f"(d[3])
        : "r"(a[0]), "r"(a[1]), "r"(a[2]), "r"(a[3]), "r"(b0), "r"(b1));
}

// ---------------- prep kernels ----------------
__global__ void prep_w(const float* __restrict__ w,
                       const float* __restrict__ p,
                       const float* __restrict__ q) {
    __shared__ float red[4];
    const int co = blockIdx.x;
    const int tid = threadIdx.x;  // 128
    const float* wr = w + co * KTOT;  // layout [Cin][3][3] per cout
    float ssum = 0.f;
    for (int i = tid; i < KTOT; i += 128) { const float v = wr[i]; ssum += v * v; }
    #pragma unroll
    for (int o = 16; o; o >>= 1) ssum += __shfl_xor_sync(0xffffffff, ssum, o);
    if ((tid & 31) == 0) red[tid >> 5] = ssum;
    __syncthreads();
    const float tot = red[0] + red[1] + red[2] + red[3];
    const float qv = q[0] * 0.01f;
    const float qs = qv * qv;
    const float scale = 1.f / (sqrtf(tot) + EPSF + qs);
    for (int i = tid; i < KTOT; i += 128) {
        const int cin = i / 9;
        const int t = i - cin * 9;
        const int k = t * 128 + cin;     // reordered K axis
        g_Ah[co * KTOT + k] = __float2half(wr[i] * scale);
    }
    if (tid == 0) { const float pv = p[co] * 0.1f; g_psqr[co] = pv * pv; }
}

// x[b][cin][h][w] -> xT[b][h][w][cin] fp16, plus partial x^2 sums over the
// 32-cin chunk into g_s4[chunk]. 32x32 tiled transpose.
__global__ void __launch_bounds__(256)
prep_split(const float* __restrict__ x) {
    __shared__ float xs[32][33];
    const int b  = blockIdx.z;
    const int yc = blockIdx.y;        // cin chunk 0..3
    const int c0 = yc * 32;
    const int p0 = blockIdx.x * 32;   // hw tile base
    const int tx = threadIdx.x & 31, ty = threadIdx.x >> 5;  // 32 x 8

    #pragma unroll
    for (int i = 0; i < 4; ++i) {
        const int c = ty + i * 8;
        xs[c][tx] = x[((size_t)b * CIN + c0 + c) * 4096 + p0 + tx];
    }
    __syncthreads();

    const int p  = threadIdx.x >> 3;       // pixel within tile
    const int g4 = (threadIdx.x & 7) * 4;  // cin group of 4
    uint2 hv;
    __half* ph = (__half*)&hv;
    float part = 0.f;
    #pragma unroll
    for (int j = 0; j < 4; ++j) {
        const float v = xs[g4 + j][p];
        ph[j] = __float2half(v);
        part += v * v;
    }
    const size_t o = ((size_t)b * 4096 + p0 + p) * CIN + c0 + g4;
    *(uint2*)((char*)g_xh + o * 2) = hv;

    // reduce 8 lanes (same pixel) -> partial sum of this 32-cin chunk
    part += __shfl_xor_sync(0xffffffff, part, 1);
    part += __shfl_xor_sync(0xffffffff, part, 2);
    part += __shfl_xor_sync(0xffffffff, part, 4);
    if ((threadIdx.x & 7) == 0)
        g_s4[yc][(size_t)b * 4096 + p0 + p] = part;
}

__global__ void prep_invden(const float* __restrict__ q) {
    const int i = blockIdx.x * 256 + threadIdx.x;
    const int b = i >> 12;
    const int hw = i & 4095;
    const int h = hw >> 6, w = hw & 63;
    float acc = 0.f;
    #pragma unroll
    for (int dh = -1; dh <= 1; ++dh) {
        const int hh = h + dh;
        if ((unsigned)hh >= (unsigned)HH) continue;
        #pragma unroll
        for (int dw = -1; dw <= 1; ++dw) {
            const int w2 = w + dw;
            if ((unsigned)w2 >= (unsigned)WW) continue;
            const int idx = b * 4096 + hh * 64 + w2;
            acc += g_s4[0][idx] + g_s4[1][idx] + g_s4[2][idx] + g_s4[3][idx];
        }
    }
    const float qv = q[0] * 0.01f;
    const float qs = qv * qv;
    g_invden[i] = 1.f / (sqrtf(acc + EPSF) + qs);
}

// ---------------- GEMM + fused epilogue ----------------
static __device__ __forceinline__ float scs_act(float y, float psqr) {
    const float sg = __fdividef(1.f, 1.f + __expf(-y));
    const float mag = exp2f(psqr * __log2f(fabsf(y) + EPSF));
    return sg * mag;
}

__global__ void __launch_bounds__(256, 2)
conv_mma(float* __restrict__ out) {
    extern __shared__ char smem[];
    const uint32_t sbase = smem_u32(smem);
    const int tid = threadIdx.x;
    const int lane = tid & 31;
    const int wid = tid >> 5;
    const int warp_m = wid >> 2;    // 0..1
    const int warp_n = wid & 3;     // 0..3
    const int m0 = blockIdx.x * MT;
    const int n0 = blockIdx.y * NT;

    // ---- hoisted per-thread staging state ----
    // each thread owns 16B chunk c8 of rows {r0, r0+32, r0+64, r0+96}
    const int c8 = tid & 7;
    const int r0 = tid >> 3;                 // 0..31
    const uint32_t soff = r0 * ROWB + c8 * 16;
    const int b  = n0 >> 12;
    const int h0 = (n0 & 4095) >> 6;         // first of 2 output rows
    const char* gA = (const char*)g_Ah + ((size_t)(m0 + r0) * KTOT) * 2 + c8 * 16;
    const char* gB = (const char*)g_xh
                   + (((size_t)b * 4096 + h0 * 64 + r0) * CIN + c8 * 8) * 2;
    // halo validity: reps 0/1 at row h0, reps 2/3 at row h0+1;
    // reps 0/2 at cols 0..31 (w=r0), reps 1/3 at cols 32..63 (w=32+r0)
    const bool bh0 = h0 > 0, bh1 = h0 < 62, bwe = r0 > 0, bwo = r0 < 31;

    auto stage = [&](int s, int pk) {
        const uint32_t sb = sbase + s * STAGE_BYTES;
        #pragma unroll
        for (int rep = 0; rep < 4; ++rep)
            CP_ASYNC16(sb + soff + rep * (32 * ROWB),
                       gA + rep * (32 * KTOT * 2));
        const int tap = pk >> 1;
        const int t3 = tap / 3;
        const int dh = t3 - 1;
        const int dw = tap - t3 * 3 - 1;
        const int d  = (dh * 64 + dw) * (CIN * 2) + (pk & 1) * (64 * 2);
        const bool okh01 = (dh >= 0) | bh0;
        const bool okh23 = (dh <= 0) | bh1;
        const bool okwe  = (dw >= 0) | bwe;
        const bool okwo  = (dw <= 0) | bwo;
        const bool ok[4] = { okh01 && okwe, okh01 && okwo,
                             okh23 && okwe, okh23 && okwo };
        #pragma unroll
        for (int rep = 0; rep < 4; ++rep) {
            // rep pixel offsets {0,32,64,96} -> {0,8192,16384,24576} bytes
            const char* g = ok[rep] ? (gB + d + rep * 8192) : (const char*)g_xh;
            CP_ASYNC16_Z(sb + TILEB + soff + rep * (32 * ROWB), g,
                         ok[rep] ? 16 : 0);
        }
        CP_COMMIT();
        gA += KC * 2;   // advance to next staged kit
    };

    float acc[4][4][4];
    #pragma unroll
    for (int i = 0; i < 4; ++i)
        #pragma unroll
        for (int j = 0; j < 4; ++j)
            #pragma unroll
            for (int k = 0; k < 4; ++k) acc[i][j][k] = 0.f;

    stage(0, 0);
    stage(1, 1);

    const int lrow = lane & 15;
    const int lkg  = lane >> 4;

    int s_cur = 0;   // buffer holding stage kit
    int s_pf  = 2;   // buffer to prefetch kit+2 into

    #pragma unroll 1
    for (int kit = 0; kit < NKIT; ++kit) {
        if (kit < NKIT - 1) CP_WAIT(1); else CP_WAIT(0);
        __syncthreads();   // stage kit visible; readers of buffer s_pf (kit-1) done

        if (kit + 2 < NKIT)
            stage(s_pf, kit + 2);

        const uint32_t sb = sbase + s_cur * STAGE_BYTES;
        const uint32_t sB = sb + TILEB;

        #pragma unroll
        for (int ks = 0; ks < 4; ++ks) {
            const uint32_t kb = ks * 32 + lkg * 16;
            uint32_t bh[2][4];
            #pragma unroll
            for (int np = 0; np < 2; ++np) {
                const uint32_t boff = (warp_n * 32 + np * 16 + lrow) * ROWB + kb;
                LDSM4(bh[np][0], bh[np][1], bh[np][2], bh[np][3], sB + boff);
            }
            #pragma unroll
            for (int ma = 0; ma < 4; ++ma) {
                const uint32_t aoff = (warp_m * 64 + ma * 16 + lrow) * ROWB + kb;
                uint32_t ah[4];
                LDSM4(ah[0], ah[1], ah[2], ah[3], sb + aoff);
                #pragma unroll
                for (int na = 0; na < 4; ++na) {
                    const int np = na >> 1;
                    const int hi = na & 1;  // 0: {r0,r2}, 1: {r1,r3}
                    mma_f16(acc[ma][na], ah, bh[np][hi], bh[np][hi + 2]);
                }
            }
        }
        s_cur = (s_cur == 2) ? 0 : s_cur + 1;
        s_pf  = (s_pf == 2) ? 0 : s_pf + 1;
    }

    // ---- epilogue ----
    const int hwbase = n0 & 4095;
    #pragma unroll
    for (int ma = 0; ma < 4; ++ma) {
        const int mrow = warp_m * 64 + ma * 16 + (lane >> 2);
        #pragma unroll
        for (int na = 0; na < 4; ++na) {
            const int nloc = warp_n * 32 + na * 8 + 2 * (lane & 3);
            const float2 inv = *(const float2*)&g_invden[n0 + nloc];
            #pragma unroll
            for (int h = 0; h < 2; ++h) {
                const int co = m0 + mrow + h * 8;
                const float psqr = g_psqr[co];
                float2 o2;
                o2.x = scs_act(acc[ma][na][h * 2 + 0] * inv.x, psqr);
                o2.y = scs_act(acc[ma][na][h * 2 + 1] * inv.y, psqr);
                *(float2*)&out[(((size_t)b * COUT + co) << 12) + hwbase + nloc] = o2;
            }
        }
    }
}

// ---------------- launch ----------------
extern "C" void kernel_launch(void* const* d_in, const int* in_sizes, int n_in,
                              void* d_out, int out_size) {
    const float *x = nullptr, *w = nullptr, *p = nullptr, *q = nullptr;
    for (int i = 0; i < n_in; ++i) {
        const int sz = in_sizes[i];
        if (sz == BB * CIN * HH * WW)      x = (const float*)d_in[i];
        else if (sz == COUT * CIN * 9)     w = (const float*)d_in[i];
        else if (sz == COUT)               p = (const float*)d_in[i];
        else if (sz == 1)                  q = (const float*)d_in[i];
    }
    float* out = (float*)d_out;

    cudaFuncSetAttribute(conv_mma, cudaFuncAttributeMaxDynamicSharedMemorySize,
                         SMEM_TOTAL);

    prep_w<<<COUT, 128>>>(w, p, q);
    prep_split<<<dim3(128, 4, 32), 256>>>(x);
    prep_invden<<<NTOT / 256, 256>>>(q);

    dim3 grid(2, NTOT / NT);  // M fastest: both M-tiles of an N-tile adjacent (L2 reuse of B)
    conv_mma<<<grid, 256, SMEM_TOTAL>>>(out);
}

// round 17
// speedup vs baseline: 1.2753x; 1.0124x over previous
#include <cuda_runtime.h>
#include <cuda_fp16.h>
#include <cstdint>

// SharpenedCosineSimilarity forward via single-product fp16 mma.sync GEMM with
// implicit im2col. Warp tile 64x32, 3-stage cp.async pipeline (kit-loop
// unrolled x3 so stage indices are compile-time), B-fragments double-buffered
// across ks to break the LDSM->HMMA dependency chain.
// GEMM view: M=Cout=256, N=B*H*W=131072, K=Cin*9=1152 (k = tap*128 + cin).

#define CIN   128
#define COUT  256
#define HH    64
#define WW    64
#define BB    32
#define KTOT  1152
#define NTOT  (BB*HH*WW)
#define EPSF  1e-12f

#define MT    128
#define NT    128
#define KC    64
#define NKIT  (KTOT/KC)      // 18

#define ROWB  144            // bytes per smem row: 128 data + 16 pad (conflict-free ldmatrix)
#define TILEB (128*ROWB)     // one 128-row tile = 18432 B
#define STAGE_BYTES (2*TILEB) // A|B = 36864 B
#define SMEM_TOTAL  (3*STAGE_BYTES)   // 110592 B (3 stages)

// ---------------- device scratch (static; no allocations) ----------------
__device__ __half g_Ah[COUT * KTOT];           // weights fp16, k = tap*128+cin
__device__ __half g_xh[(size_t)NTOT * CIN];    // channel-last x fp16 (33.5MB, L2-resident)
__device__ float g_psqr[COUT];
__device__ float g_s4[4][NTOT];                // partial sum_c x^2 (32 cins each)
__device__ float g_invden[NTOT];

// ---------------- PTX helpers ----------------
static __device__ __forceinline__ uint32_t smem_u32(const void* p) {
    uint32_t a;
    asm("{ .reg .u64 t; cvta.to.shared.u64 t, %1; cvt.u32.u64 %0, t; }" : "=r"(a) : "l"(p));
    return a;
}
#define CP_ASYNC16(s, g) \
    asm volatile("cp.async.cg.shared.global [%0], [%1], 16;" :: "r"(s), "l"(g) : "memory")
#define CP_ASYNC16_Z(s, g, sz) \
    asm volatile("cp.async.cg.shared.global [%0], [%1], 16, %2;" :: "r"(s), "l"(g), "r"(sz) : "memory")
#define CP_COMMIT()  asm volatile("cp.async.commit_group;" ::: "memory")
#define CP_WAIT(n)   asm volatile("cp.async.wait_group %0;" :: "n"(n) : "memory")

#define LDSM4(r0, r1, r2, r3, a) \
    asm volatile("ldmatrix.sync.aligned.m8n8.x4.shared.b16 {%0,%1,%2,%3}, [%4];" \
        : "=r"(r0), "=r"(r1), "=r"(r2), "=r"(r3) : "r"(a))

static __device__ __forceinline__ void mma_f16(float* d, const uint32_t* a,
                                               uint32_t b0, uint32_t b1) {
    asm volatile(
        "mma.sync.aligned.m16n8k16.row.col.f32.f16.f16.f32 "
        "{%0,%1,%2,%3}, {%4,%5,%6,%7}, {%8,%9}, {%0,%1,%2,%3};"
        : "+f"(d[0]), "+f"(d[1]), "+f"(d[2]), "+f"(d[3])
        : "r"(a[0]), "r"(a[1]), "r"(a[2]), "r"(a[3]), "r"(b0), "r"(b1));
}

// ---------------- prep kernels ----------------
__global__ void prep_w(const float* __restrict__ w,
                       const float* __restrict__ p,
                       const float* __restrict__ q) {
    __shared__ float red[4];
    const int co = blockIdx.x;
    const int tid = threadIdx.x;  // 128
    const float* wr = w + co * KTOT;  // layout [Cin][3][3] per cout
    float ssum = 0.f;
    for (int i = tid; i < KTOT; i += 128) { const float v = wr[i]; ssum += v * v; }
    #pragma unroll
    for (int o = 16; o; o >>= 1) ssum += __shfl_xor_sync(0xffffffff, ssum, o);
    if ((tid & 31) == 0) red[tid >> 5] = ssum;
    __syncthreads();
    const float tot = red[0] + red[1] + red[2] + red[3];
    const float qv = q[0] * 0.01f;
    const float qs = qv * qv;
    const float scale = 1.f / (sqrtf(tot) + EPSF + qs);
    for (int i = tid; i < KTOT; i += 128) {
        const int cin = i / 9;
        const int t = i - cin * 9;
        const int k = t * 128 + cin;     // reordered K axis
        g_Ah[co * KTOT + k] = __float2half(wr[i] * scale);
    }
    if (tid == 0) { const float pv = p[co] * 0.1f; g_psqr[co] = pv * pv; }
}

// x[b][cin][h][w] -> xT[b][h][w][cin] fp16, plus partial x^2 sums over the
// 32-cin chunk into g_s4[chunk]. 32x32 tiled transpose.
__global__ void __launch_bounds__(256)
prep_split(const float* __restrict__ x) {
    __shared__ float xs[32][33];
    const int b  = blockIdx.z;
    const int yc = blockIdx.y;        // cin chunk 0..3
    const int c0 = yc * 32;
    const int p0 = blockIdx.x * 32;   // hw tile base
    const int tx = threadIdx.x & 31, ty = threadIdx.x >> 5;  // 32 x 8

    #pragma unroll
    for (int i = 0; i < 4; ++i) {
        const int c = ty + i * 8;
        xs[c][tx] = x[((size_t)b * CIN + c0 + c) * 4096 + p0 + tx];
    }
    __syncthreads();

    const int p  = threadIdx.x >> 3;       // pixel within tile
    const int g4 = (threadIdx.x & 7) * 4;  // cin group of 4
    uint2 hv;
    __half* ph = (__half*)&hv;
    float part = 0.f;
    #pragma unroll
    for (int j = 0; j < 4; ++j) {
        const float v = xs[g4 + j][p];
        ph[j] = __float2half(v);
        part += v * v;
    }
    const size_t o = ((size_t)b * 4096 + p0 + p) * CIN + c0 + g4;
    *(uint2*)((char*)g_xh + o * 2) = hv;

    // reduce 8 lanes (same pixel) -> partial sum of this 32-cin chunk
    part += __shfl_xor_sync(0xffffffff, part, 1);
    part += __shfl_xor_sync(0xffffffff, part, 2);
    part += __shfl_xor_sync(0xffffffff, part, 4);
    if ((threadIdx.x & 7) == 0)
        g_s4[yc][(size_t)b * 4096 + p0 + p] = part;
}

__global__ void prep_invden(const float* __restrict__ q) {
    const int i = blockIdx.x * 256 + threadIdx.x;
    const int b = i >> 12;
    const int hw = i & 4095;
    const int h = hw >> 6, w = hw & 63;
    float acc = 0.f;
    #pragma unroll
    for (int dh = -1; dh <= 1; ++dh) {
        const int hh = h + dh;
        if ((unsigned)hh >= (unsigned)HH) continue;
        #pragma unroll
        for (int dw = -1; dw <= 1; ++dw) {
            const int w2 = w + dw;
            if ((unsigned)w2 >= (unsigned)WW) continue;
            const int idx = b * 4096 + hh * 64 + w2;
            acc += g_s4[0][idx] + g_s4[1][idx] + g_s4[2][idx] + g_s4[3][idx];
        }
    }
    const float qv = q[0] * 0.01f;
    const float qs = qv * qv;
    g_invden[i] = 1.f / (sqrtf(acc + EPSF) + qs);
}

// ---------------- GEMM + fused epilogue ----------------
static __device__ __forceinline__ float scs_act(float y, float psqr) {
    const float sg = __fdividef(1.f, 1.f + __expf(-y));
    const float mag = exp2f(psqr * __log2f(fabsf(y) + EPSF));
    return sg * mag;
}

__global__ void __launch_bounds__(256, 2)
conv_mma(float* __restrict__ out) {
    extern __shared__ char smem[];
    const uint32_t sbase = smem_u32(smem);
    const int tid = threadIdx.x;
    const int lane = tid & 31;
    const int wid = tid >> 5;
    const int warp_m = wid >> 2;    // 0..1
    const int warp_n = wid & 3;     // 0..3
    const int m0 = blockIdx.x * MT;
    const int n0 = blockIdx.y * NT;

    // ---- hoisted per-thread staging state ----
    const int c8 = tid & 7;
    const int r0 = tid >> 3;                 // 0..31
    const uint32_t soff = r0 * ROWB + c8 * 16;
    const int b  = n0 >> 12;
    const int h0 = (n0 & 4095) >> 6;         // first of 2 output rows
    const char* gA = (const char*)g_Ah + ((size_t)(m0 + r0) * KTOT) * 2 + c8 * 16;
    const char* gB = (const char*)g_xh
                   + (((size_t)b * 4096 + h0 * 64 + r0) * CIN + c8 * 8) * 2;
    const bool bh0 = h0 > 0, bh1 = h0 < 62, bwe = r0 > 0, bwo = r0 < 31;

    auto stage = [&](int s, int pk) {
        const uint32_t sb = sbase + s * STAGE_BYTES;
        #pragma unroll
        for (int rep = 0; rep < 4; ++rep)
            CP_ASYNC16(sb + soff + rep * (32 * ROWB),
                       gA + rep * (32 * KTOT * 2));
        const int tap = pk >> 1;
        const int t3 = tap / 3;
        const int dh = t3 - 1;
        const int dw = tap - t3 * 3 - 1;
        const int d  = (dh * 64 + dw) * (CIN * 2) + (pk & 1) * (64 * 2);
        const bool okh01 = (dh >= 0) | bh0;
        const bool okh23 = (dh <= 0) | bh1;
        const bool okwe  = (dw >= 0) | bwe;
        const bool okwo  = (dw <= 0) | bwo;
        const bool ok[4] = { okh01 && okwe, okh01 && okwo,
                             okh23 && okwe, okh23 && okwo };
        #pragma unroll
        for (int rep = 0; rep < 4; ++rep) {
            const char* g = ok[rep] ? (gB + d + rep * 8192) : (const char*)g_xh;
            CP_ASYNC16_Z(sb + TILEB + soff + rep * (32 * ROWB), g,
                         ok[rep] ? 16 : 0);
        }
        CP_COMMIT();
        gA += KC * 2;   // advance to next staged kit
    };

    float acc[4][4][4];
    #pragma unroll
    for (int i = 0; i < 4; ++i)
        #pragma unroll
        for (int j = 0; j < 4; ++j)
            #pragma unroll
            for (int k = 0; k < 4; ++k) acc[i][j][k] = 0.f;

    stage(0, 0);
    stage(1, 1);

    const int lrow = lane & 15;
    const int lkg  = lane >> 4;
    // per-warp LDSM base offsets (ldmatrix becomes [base + imm])
    const uint32_t aW = (warp_m * 64 + lrow) * ROWB + lkg * 16;
    const uint32_t bW = (warp_n * 32 + lrow) * ROWB + lkg * 16;

    // one kit of compute on stage buffer s (compile-time), prefetching into pf
    auto kit_body = [&](int s, int pf, int kit) {
        if (kit < NKIT - 1) CP_WAIT(1); else CP_WAIT(0);
        __syncthreads();

        if (kit + 2 < NKIT) stage(pf, kit + 2);

        const uint32_t sA = sbase + s * STAGE_BYTES + aW;
        const uint32_t sB = sbase + s * STAGE_BYTES + TILEB + bW;

        uint32_t bfr[2][2][4];
        #pragma unroll
        for (int np = 0; np < 2; ++np)
            LDSM4(bfr[0][np][0], bfr[0][np][1], bfr[0][np][2], bfr[0][np][3],
                  sB + np * (16 * ROWB));

        #pragma unroll
        for (int ks = 0; ks < 4; ++ks) {
            const int cur = ks & 1, nxt = cur ^ 1;
            if (ks < 3) {
                #pragma unroll
                for (int np = 0; np < 2; ++np)
                    LDSM4(bfr[nxt][np][0], bfr[nxt][np][1],
                          bfr[nxt][np][2], bfr[nxt][np][3],
                          sB + np * (16 * ROWB) + (ks + 1) * 32);
            }
            #pragma unroll
            for (int ma = 0; ma < 4; ++ma) {
                uint32_t ah[4];
                LDSM4(ah[0], ah[1], ah[2], ah[3],
                      sA + ma * (16 * ROWB) + ks * 32);
                #pragma unroll
                for (int na = 0; na < 4; ++na) {
                    const int np = na >> 1;
                    const int hi = na & 1;  // 0: {r0,r2}, 1: {r1,r3}
                    mma_f16(acc[ma][na], ah, bfr[cur][np][hi],
                            bfr[cur][np][hi + 2]);
                }
            }
        }
    };

    // NKIT = 18 = 6 x 3; stage rotation has period 3 -> compile-time indices
    #pragma unroll 1
    for (int kit3 = 0; kit3 < NKIT / 3; ++kit3) {
        const int kit = kit3 * 3;
        kit_body(0, 2, kit + 0);
        kit_body(1, 0, kit + 1);
        kit_body(2, 1, kit + 2);
    }

    // ---- epilogue ----
    const int hwbase = n0 & 4095;
    #pragma unroll
    for (int ma = 0; ma < 4; ++ma) {
        const int mrow = warp_m * 64 + ma * 16 + (lane >> 2);
        #pragma unroll
        for (int na = 0; na < 4; ++na) {
            const int nloc = warp_n * 32 + na * 8 + 2 * (lane & 3);
            const float2 inv = *(const float2*)&g_invden[n0 + nloc];
            #pragma unroll
            for (int h = 0; h < 2; ++h) {
                const int co = m0 + mrow + h * 8;
                const float psqr = g_psqr[co];
                float2 o2;
                o2.x = scs_act(acc[ma][na][h * 2 + 0] * inv.x, psqr);
                o2.y = scs_act(acc[ma][na][h * 2 + 1] * inv.y, psqr);
                *(float2*)&out[(((size_t)b * COUT + co) << 12) + hwbase + nloc] = o2;
            }
        }
    }
}

// ---------------- launch ----------------
extern "C" void kernel_launch(void* const* d_in, const int* in_sizes, int n_in,
                              void* d_out, int out_size) {
    const float *x = nullptr, *w = nullptr, *p = nullptr, *q = nullptr;
    for (int i = 0; i < n_in; ++i) {
        const int sz = in_sizes[i];
        if (sz == BB * CIN * HH * WW)      x = (const float*)d_in[i];
        else if (sz == COUT * CIN * 9)     w = (const float*)d_in[i];
        else if (sz == COUT)               p = (const float*)d_in[i];
        else if (sz == 1)                  q = (const float*)d_in[i];
    }
    float* out = (float*)d_out;

    cudaFuncSetAttribute(conv_mma, cudaFuncAttributeMaxDynamicSharedMemorySize,
                         SMEM_TOTAL);

    prep_w<<<COUT, 128>>>(w, p, q);
    prep_split<<<dim3(128, 4, 32), 256>>>(x);
    prep_invden<<<NTOT / 256, 256>>>(q);

    dim3 grid(2, NTOT / NT);  // M fastest: both M-tiles of an N-tile adjacent (L2 reuse of B)
    conv_mma<<<grid, 256, SMEM_TOTAL>>>(out);
}